// round 11
// baseline (speedup 1.0000x reference)
#include <cuda_runtime.h>
#include <cuda_bf16.h>
#include <math.h>

#define NN 100000
#define NE 1600000
#define DD 512
#define HH 256
#define KK 64
#define SCAN_B 256
#define SCAN_NB ((NN + SCAN_B - 1) / SCAN_B)   // 391

// Scratch: __device__ globals, referenced ONLY from device code.
__device__ float4 g_hw4[(size_t)NN * HH / 4];   // GEMM output (message source)
__device__ float4 g_h4 [(size_t)NN * HH / 4];   // hidden state (layer 1)
__device__ float4 g_h24[(size_t)NN * HH / 4];   // hidden state (layer 2)
__device__ float  g_dinv[NN];                   // rsqrt(deg)
__device__ int    g_deg[NN];                    // in-degree (excl self)
__device__ int    g_off[NN + 1];                // CSR row offsets (by dst)
__device__ int    g_cur[NN];                    // fill cursors
__device__ int    g_csr[NE];                    // CSR src indices
__device__ int    g_blocksum[SCAN_NB];          // scan partials
__device__ int    g_is64;                       // edge_index dtype flag

// ---------------------------------------------------------------------------
// Edge dtype detection
// ---------------------------------------------------------------------------
__global__ void k_detect(const int* ei_raw) {
    if (threadIdx.x == 0 && blockIdx.x == 0) {
        int all0 = 1;
        for (int i = 0; i < 64; i++)
            if (ei_raw[2 * i + 1] != 0) { all0 = 0; break; }
        g_is64 = all0;
    }
}

__device__ __forceinline__ int edge_at(const int* ei_raw, size_t idx) {
    return g_is64 ? ei_raw[2 * idx] : ei_raw[idx];
}

// ---------------------------------------------------------------------------
// CSR build: degree count -> scan -> fill. Also dinv = rsqrt(deg+1).
// ---------------------------------------------------------------------------
__global__ void k_zero() {
    int i = blockIdx.x * blockDim.x + threadIdx.x;
    if (i < NN) { g_deg[i] = 0; g_cur[i] = 0; }
}

__global__ void k_deg_count(const int* ei_raw) {
    int e = blockIdx.x * blockDim.x + threadIdx.x;
    if (e >= NE) return;
    int d = edge_at(ei_raw, (size_t)NE + e);
    if (d >= 0 && d < NN) atomicAdd(&g_deg[d], 1);
}

__global__ void k_dinv() {
    int i = blockIdx.x * blockDim.x + threadIdx.x;
    if (i < NN) g_dinv[i] = rsqrtf((float)(g_deg[i] + 1));
}

// per-block reduce of degrees
__global__ void k_scan_reduce() {
    __shared__ int sh[SCAN_B];
    int i = blockIdx.x * SCAN_B + threadIdx.x;
    sh[threadIdx.x] = (i < NN) ? g_deg[i] : 0;
    __syncthreads();
    for (int s = SCAN_B / 2; s > 0; s >>= 1) {
        if (threadIdx.x < s) sh[threadIdx.x] += sh[threadIdx.x + s];
        __syncthreads();
    }
    if (threadIdx.x == 0) g_blocksum[blockIdx.x] = sh[0];
}

// parallel exclusive scan of 391 block sums (one block, 512 threads)
__global__ void k_scan_bases() {
    __shared__ int sh[512];
    int i = threadIdx.x;
    int v = (i < SCAN_NB) ? g_blocksum[i] : 0;
    sh[i] = v;
    __syncthreads();
    for (int s = 1; s < 512; s <<= 1) {
        int t = (i >= s) ? sh[i - s] : 0;
        __syncthreads();
        sh[i] += t;
        __syncthreads();
    }
    if (i < SCAN_NB) g_blocksum[i] = sh[i] - v;   // exclusive
    if (i == SCAN_NB - 1) g_off[NN] = sh[i];      // total == NE
}

// per-block exclusive scan + base -> g_off
__global__ void k_scan_offsets() {
    __shared__ int sh[SCAN_B];
    int i = blockIdx.x * SCAN_B + threadIdx.x;
    int v = (i < NN) ? g_deg[i] : 0;
    sh[threadIdx.x] = v;
    __syncthreads();
    for (int s = 1; s < SCAN_B; s <<= 1) {
        int t = (threadIdx.x >= s) ? sh[threadIdx.x - s] : 0;
        __syncthreads();
        sh[threadIdx.x] += t;
        __syncthreads();
    }
    if (i < NN) g_off[i] = g_blocksum[blockIdx.x] + sh[threadIdx.x] - v;
}

__global__ void k_fill(const int* ei_raw) {
    int e = blockIdx.x * blockDim.x + threadIdx.x;
    if (e >= NE) return;
    int s = edge_at(ei_raw, (size_t)e);
    int d = edge_at(ei_raw, (size_t)NE + e);
    if ((unsigned)s >= NN || (unsigned)d >= NN) return;
    int pos = g_off[d] + atomicAdd(&g_cur[d], 1);
    g_csr[pos] = s;
}

// ---------------------------------------------------------------------------
// Split-bf16 tensor GEMM, double-buffered software pipeline.
// C = op(A) @ B; x = hi+lo bf16; acc += lo*hi' + hi*lo' + hi*hi' (fp32).
// BM=128, BK=16, BN template (64 or 128). THREADS = 4*BN.
// Warps: 4(m) x BN/32(n); warp tile 32x32 (identical frag layout to prior
// validated round). One __syncthreads per K-step via ping-pong smem.
// ---------------------------------------------------------------------------
__device__ __forceinline__ void split2(float a, float b, unsigned& hi, unsigned& lo) {
    __nv_bfloat16 ha = __float2bfloat16(a);
    __nv_bfloat16 hb = __float2bfloat16(b);
    __nv_bfloat16 la = __float2bfloat16(a - __bfloat162float(ha));
    __nv_bfloat16 lb = __float2bfloat16(b - __bfloat162float(hb));
    hi = (unsigned)__bfloat16_as_ushort(ha) | ((unsigned)__bfloat16_as_ushort(hb) << 16);
    lo = (unsigned)__bfloat16_as_ushort(la) | ((unsigned)__bfloat16_as_ushort(lb) << 16);
}

template<int BN, bool RELU_A, int A_SRC, int C_DST>
__global__ void __launch_bounds__(4 * BN)
k_mma_gemm(const float* Aext, const float* B, float* Cext, int M, int Kc, int Nc) {
    constexpr int BM = 128, BK = 16;
    constexpr int THREADS = 4 * BN;
    constexpr int WN = BN / 32;                       // warps along n
    constexpr int ALOADS = (BM * BK / 4) / THREADS;   // f4 per thread for A

    const float* A = (A_SRC == 1) ? (const float*)g_h4
                   : (A_SRC == 2) ? (const float*)g_h24 : Aext;
    float*       C = (C_DST == 1) ? (float*)g_hw4       : Cext;

    __shared__ unsigned AsH[2][BM][BK / 2 + 1], AsL[2][BM][BK / 2 + 1];
    __shared__ unsigned BsH[2][BK / 2][BN + 1], BsL[2][BK / 2][BN + 1];

    int tid  = threadIdx.x;
    int wid  = tid >> 5;
    int lane = tid & 31;
    int wm   = wid / WN;
    int wn   = wid % WN;
    int brow = blockIdx.y * BM;
    int bcol = blockIdx.x * BN;

    float acc[2][4][4];
    #pragma unroll
    for (int i = 0; i < 2; i++)
        #pragma unroll
        for (int j = 0; j < 4; j++)
            #pragma unroll
            for (int r = 0; r < 4; r++) acc[i][j][r] = 0.0f;

    float4 pa[ALOADS];
    float4 pb0, pb1;
    const bool bload = (tid < 2 * BN);
    int br2 = 0, bbc = 0;
    if (bload) { br2 = tid / (BN / 4); bbc = (tid % (BN / 4)) * 4; }

    auto load_tile = [&](int k0) {
        #pragma unroll
        for (int l = 0; l < ALOADS; l++) {
            int f  = tid + l * THREADS;
            int ar = f >> 2;
            int ak = (f & 3) << 2;
            int gr = brow + ar;
            float4 v = make_float4(0.f, 0.f, 0.f, 0.f);
            if (gr < M) v = *(const float4*)(A + (size_t)gr * Kc + k0 + ak);
            if (RELU_A) {
                v.x = fmaxf(v.x, 0.f); v.y = fmaxf(v.y, 0.f);
                v.z = fmaxf(v.z, 0.f); v.w = fmaxf(v.w, 0.f);
            }
            pa[l] = v;
        }
        if (bload) {
            pb0 = *(const float4*)(B + (size_t)(k0 + 2 * br2    ) * Nc + bcol + bbc);
            pb1 = *(const float4*)(B + (size_t)(k0 + 2 * br2 + 1) * Nc + bcol + bbc);
        }
    };
    auto store_tile = [&](int buf) {
        #pragma unroll
        for (int l = 0; l < ALOADS; l++) {
            int f  = tid + l * THREADS;
            int ar = f >> 2;
            int k2 = ((f & 3) << 2) >> 1;
            split2(pa[l].x, pa[l].y, AsH[buf][ar][k2    ], AsL[buf][ar][k2    ]);
            split2(pa[l].z, pa[l].w, AsH[buf][ar][k2 + 1], AsL[buf][ar][k2 + 1]);
        }
        if (bload) {
            split2(pb0.x, pb1.x, BsH[buf][br2][bbc + 0], BsL[buf][br2][bbc + 0]);
            split2(pb0.y, pb1.y, BsH[buf][br2][bbc + 1], BsL[buf][br2][bbc + 1]);
            split2(pb0.z, pb1.z, BsH[buf][br2][bbc + 2], BsL[buf][br2][bbc + 2]);
            split2(pb0.w, pb1.w, BsH[buf][br2][bbc + 3], BsL[buf][br2][bbc + 3]);
        }
    };

    load_tile(0);
    store_tile(0);
    __syncthreads();

    int p = 0;
    for (int k0 = 0; k0 < Kc; k0 += BK) {
        bool hn = (k0 + BK) < Kc;
        if (hn) load_tile(k0 + BK);

        {
            int t = lane & 3;
            int g = lane >> 2;
            unsigned ah[2][4], al[2][4];
            #pragma unroll
            for (int fm = 0; fm < 2; fm++) {
                int r0 = wm * 32 + fm * 16 + g;
                ah[fm][0] = AsH[p][r0    ][t    ];
                ah[fm][1] = AsH[p][r0 + 8][t    ];
                ah[fm][2] = AsH[p][r0    ][t + 4];
                ah[fm][3] = AsH[p][r0 + 8][t + 4];
                al[fm][0] = AsL[p][r0    ][t    ];
                al[fm][1] = AsL[p][r0 + 8][t    ];
                al[fm][2] = AsL[p][r0    ][t + 4];
                al[fm][3] = AsL[p][r0 + 8][t + 4];
            }
            unsigned bh[4][2], bl[4][2];
            #pragma unroll
            for (int fn = 0; fn < 4; fn++) {
                int cc = wn * 32 + fn * 8 + g;
                bh[fn][0] = BsH[p][t    ][cc];
                bh[fn][1] = BsH[p][t + 4][cc];
                bl[fn][0] = BsL[p][t    ][cc];
                bl[fn][1] = BsL[p][t + 4][cc];
            }
            #pragma unroll
            for (int fm = 0; fm < 2; fm++)
                #pragma unroll
                for (int fn = 0; fn < 4; fn++) {
                    float* d = acc[fm][fn];
                    asm volatile(
                        "mma.sync.aligned.m16n8k16.row.col.f32.bf16.bf16.f32 "
                        "{%0,%1,%2,%3}, {%4,%5,%6,%7}, {%8,%9}, {%0,%1,%2,%3};"
                        : "+f"(d[0]), "+f"(d[1]), "+f"(d[2]), "+f"(d[3])
                        : "r"(al[fm][0]), "r"(al[fm][1]), "r"(al[fm][2]), "r"(al[fm][3]),
                          "r"(bh[fn][0]), "r"(bh[fn][1]));
                    asm volatile(
                        "mma.sync.aligned.m16n8k16.row.col.f32.bf16.bf16.f32 "
                        "{%0,%1,%2,%3}, {%4,%5,%6,%7}, {%8,%9}, {%0,%1,%2,%3};"
                        : "+f"(d[0]), "+f"(d[1]), "+f"(d[2]), "+f"(d[3])
                        : "r"(ah[fm][0]), "r"(ah[fm][1]), "r"(ah[fm][2]), "r"(ah[fm][3]),
                          "r"(bl[fn][0]), "r"(bl[fn][1]));
                    asm volatile(
                        "mma.sync.aligned.m16n8k16.row.col.f32.bf16.bf16.f32 "
                        "{%0,%1,%2,%3}, {%4,%5,%6,%7}, {%8,%9}, {%0,%1,%2,%3};"
                        : "+f"(d[0]), "+f"(d[1]), "+f"(d[2]), "+f"(d[3])
                        : "r"(ah[fm][0]), "r"(ah[fm][1]), "r"(ah[fm][2]), "r"(ah[fm][3]),
                          "r"(bh[fn][0]), "r"(bh[fn][1]));
                }
        }

        if (hn) store_tile(p ^ 1);
        __syncthreads();
        p ^= 1;
    }

    #pragma unroll
    for (int fm = 0; fm < 2; fm++) {
        int row0 = brow + wm * 32 + fm * 16 + (lane >> 2);
        #pragma unroll
        for (int half = 0; half < 2; half++) {
            int row = row0 + half * 8;
            if (row >= M) continue;
            #pragma unroll
            for (int fn = 0; fn < 4; fn++) {
                int col = bcol + wn * 32 + fn * 8 + 2 * (lane & 3);
                *(float2*)(C + (size_t)row * Nc + col) =
                    make_float2(acc[fm][fn][half * 2 + 0], acc[fm][fn][half * 2 + 1]);
            }
        }
    }
}

// ---------------------------------------------------------------------------
// CSR gather aggregation: warp per node, no atomics.
// out[node] = bias + dinv^2 * hw[node] + sum_in (dinv[n]*dinv[s]) * hw[s]
// DST: 1 = g_h, 2 = g_h2
// ---------------------------------------------------------------------------
template<int DST>
__global__ void k_agg_gather(const float* bias) {
    int gtid = blockIdx.x * blockDim.x + threadIdx.x;
    int node = gtid >> 5;
    int lane = gtid & 31;
    if (node >= NN) return;

    float di = g_dinv[node];
    float ws = di * di;
    const float4* hw = g_hw4 + (size_t)node * (HH / 4);
    float4 b0 = ((const float4*)bias)[lane];
    float4 b1 = ((const float4*)bias)[lane + 32];
    float4 v0 = hw[lane];
    float4 v1 = hw[lane + 32];
    float4 a0 = make_float4(fmaf(ws, v0.x, b0.x), fmaf(ws, v0.y, b0.y),
                            fmaf(ws, v0.z, b0.z), fmaf(ws, v0.w, b0.w));
    float4 a1 = make_float4(fmaf(ws, v1.x, b1.x), fmaf(ws, v1.y, b1.y),
                            fmaf(ws, v1.z, b1.z), fmaf(ws, v1.w, b1.w));

    int e0 = g_off[node], e1 = g_off[node + 1];
    for (int i = e0; i < e1; i++) {
        int s = g_csr[i];
        float w = di * g_dinv[s];
        const float4* hs = g_hw4 + (size_t)s * (HH / 4);
        float4 u0 = hs[lane];
        float4 u1 = hs[lane + 32];
        a0.x = fmaf(w, u0.x, a0.x); a0.y = fmaf(w, u0.y, a0.y);
        a0.z = fmaf(w, u0.z, a0.z); a0.w = fmaf(w, u0.w, a0.w);
        a1.x = fmaf(w, u1.x, a1.x); a1.y = fmaf(w, u1.y, a1.y);
        a1.z = fmaf(w, u1.z, a1.z); a1.w = fmaf(w, u1.w, a1.w);
    }

    float4* out = ((DST == 1) ? g_h4 : g_h24) + (size_t)node * (HH / 4);
    out[lane]      = a0;
    out[lane + 32] = a1;
}

// ---------------------------------------------------------------------------
// Softmax over K=64, warp per row. d_out layout: [S | logits], each NN*KK.
// ---------------------------------------------------------------------------
__global__ void k_softmax(const float* log_tau, float* out) {
    int gtid = blockIdx.x * blockDim.x + threadIdx.x;
    int row  = gtid >> 5;
    int lane = gtid & 31;
    if (row >= NN) return;
    const float* lg = out + (size_t)NN * KK + (size_t)row * KK;
    float inv_tau = __expf(-log_tau[0]);
    float a = lg[lane] * inv_tau;
    float b = lg[lane + 32] * inv_tau;
    float m = fmaxf(a, b);
    #pragma unroll
    for (int off = 16; off > 0; off >>= 1)
        m = fmaxf(m, __shfl_xor_sync(0xFFFFFFFFu, m, off));
    float e0 = __expf(a - m);
    float e1 = __expf(b - m);
    float s = e0 + e1;
    #pragma unroll
    for (int off = 16; off > 0; off >>= 1)
        s += __shfl_xor_sync(0xFFFFFFFFu, s, off);
    float inv = 1.0f / s;
    float* S = out + (size_t)row * KK;
    S[lane]      = e0 * inv;
    S[lane + 32] = e1 * inv;
}

// ---------------------------------------------------------------------------
extern "C" void kernel_launch(void* const* d_in, const int* in_sizes, int n_in,
                              void* d_out, int out_size) {
    const float* x       = (const float*)d_in[0];
    const int*   ei_raw  = (const int*)d_in[1];
    const float* W1      = (const float*)d_in[2];
    const float* b1      = (const float*)d_in[3];
    const float* W2      = (const float*)d_in[4];
    const float* b2      = (const float*)d_in[5];
    const float* Wk      = (const float*)d_in[6];
    const float* log_tau = (const float*)d_in[7];
    float* out = (float*)d_out;

    // CSR build + norms
    k_detect      <<<1, 32>>>(ei_raw);
    k_zero        <<<(NN + 255) / 256, 256>>>();
    k_deg_count   <<<(NE + 255) / 256, 256>>>(ei_raw);
    k_dinv        <<<(NN + 255) / 256, 256>>>();
    k_scan_reduce <<<SCAN_NB, SCAN_B>>>();
    k_scan_bases  <<<1, 512>>>();
    k_scan_offsets<<<SCAN_NB, SCAN_B>>>();
    k_fill        <<<(NE + 255) / 256, 256>>>(ei_raw);

    dim3 grid_H(HH / 128, (NN + 127) / 128);   // (2, 782), 512 threads
    dim3 grid_K(KK / 64, (NN + 127) / 128);    // (1, 782), 256 threads
    int agg_blocks = (NN * 32 + 255) / 256;

    // Layer 1
    k_mma_gemm<128, false, 0, 1><<<grid_H, 512>>>(x, W1, nullptr, NN, DD, HH);
    k_agg_gather<1><<<agg_blocks, 256>>>(b1);

    // Layer 2
    k_mma_gemm<128, true, 1, 1><<<grid_H, 512>>>(nullptr, W2, nullptr, NN, HH, HH);
    k_agg_gather<2><<<agg_blocks, 256>>>(b2);

    // Head
    float* logits = out + (size_t)NN * KK;
    k_mma_gemm<64, false, 2, 0><<<grid_K, 256>>>(nullptr, Wk, logits, NN, HH, KK);
    k_softmax<<<(NN + 7) / 8, 256>>>(log_tau, out);
}